// round 16
// baseline (speedup 1.0000x reference)
#include <cuda_runtime.h>
#include <cstdint>
#include <float.h>
#include <limits.h>

#define CONF_THRESH   0.25f
#define ROWS_PER_TILE 64                        // per block: 32 direct + 32 staged
#define STAGE_ROWS    32
#define STAGE_FLOATS  (STAGE_ROWS * 80)         // 2560 floats = 10 KB
#define THREADS       128
#define WARPS         (THREADS / 32)            // 4

// Scratch (__device__ globals; no cudaMalloc allowed).
__device__ float        g_partials[4096];
__device__ int          g_blockmin[4096];
__device__ unsigned int g_counter = 0;          // modulo ticket: no reset needed

__device__ __forceinline__ uint32_t smem_u32(const void* p) {
    uint32_t a;
    asm("{ .reg .u64 t; cvta.to.shared.u64 t, %1; cvt.u32.u64 %0, t; }"
        : "=r"(a) : "l"(p));
    return a;
}

__global__ void __launch_bounds__(THREADS)
fused_kernel(const float* __restrict__ post, float* __restrict__ out, int K) {
    __shared__ alignas(16) float tile[STAGE_FLOATS];
    __shared__ int   sLast;
    __shared__ float sWs[WARPS];
    __shared__ int   sWm[WARPS];

    const int tid  = threadIdx.x;
    const int lane = tid & 31;
    const int wid  = tid >> 5;
    const int sub  = tid & 3;         // quarter within a row
    const int r0   = tid >> 2;        // 0..31: this thread's row within each half

    const int rowbase = blockIdx.x * ROWS_PER_TILE;

    // ---- path 1: stage rows [32,64) via cp.async.cg (5 x 16B per thread) ----
    const float4* gstage = reinterpret_cast<const float4*>(post) +
                           ((size_t)rowbase + STAGE_ROWS) * 20;
    const uint32_t sbase = smem_u32(tile);
    #pragma unroll
    for (int k = 0; k < 5; k++) {
        const int idx = tid + k * THREADS;
        asm volatile("cp.async.cg.shared.global [%0], [%1], 16;"
                     :: "r"(sbase + idx * 16), "l"(gstage + idx) : "memory");
    }
    asm volatile("cp.async.commit_group;" ::: "memory");

    // ---- path 2 (overlapped): rows [0,32) direct LDG to registers ----
    float wsum = 0.0f;
    int   wmin = INT_MAX;
    {
        const int grow = rowbase + r0;
        const float4* rp = reinterpret_cast<const float4*>(post + (size_t)grow * 80)
                           + sub * 5;
        float m = -FLT_MAX;
        #pragma unroll
        for (int i = 0; i < 5; i++) {
            float4 v = __ldg(rp + i);
            m = fmaxf(m, fmaxf(fmaxf(v.x, v.y), fmaxf(v.z, v.w)));
        }
        m = fmaxf(m, __shfl_xor_sync(0xffffffffu, m, 1));
        m = fmaxf(m, __shfl_xor_sync(0xffffffffu, m, 2));
        if (sub == 0 && grow < K) {
            wsum = m;
            if (m < CONF_THRESH) wmin = grow;
        }
    }

    // ---- staged half: wait, then conflict-free LDS.128 row maxes ----
    asm volatile("cp.async.wait_group 0;" ::: "memory");
    __syncthreads();
    {
        const int grow = rowbase + STAGE_ROWS + r0;
        const float4* rp = reinterpret_cast<const float4*>(tile + r0 * 80) + sub * 5;
        float m = -FLT_MAX;
        #pragma unroll
        for (int i = 0; i < 5; i++) {
            float4 v = rp[i];
            m = fmaxf(m, fmaxf(fmaxf(v.x, v.y), fmaxf(v.z, v.w)));
        }
        m = fmaxf(m, __shfl_xor_sync(0xffffffffu, m, 1));
        m = fmaxf(m, __shfl_xor_sync(0xffffffffu, m, 2));
        if (sub == 0 && grow < K) {
            wsum += m;
            if (m < CONF_THRESH) wmin = min(wmin, grow);
        }
    }

    // ---- warp reduce ----
    #pragma unroll
    for (int o = 16; o > 0; o >>= 1) {
        wsum += __shfl_xor_sync(0xffffffffu, wsum, o);
        wmin  = min(wmin, __shfl_xor_sync(0xffffffffu, wmin, o));
    }
    if (lane == 0) { sWs[wid] = wsum; sWm[wid] = wmin; }
    __syncthreads();

    // ---- block reduce + ticket ----
    if (tid < 32) {
        float s  = (lane < WARPS) ? sWs[lane] : 0.0f;
        int   mn = (lane < WARPS) ? sWm[lane] : INT_MAX;
        #pragma unroll
        for (int o = 2; o > 0; o >>= 1) {
            s  += __shfl_xor_sync(0xffffffffu, s, o);
            mn  = min(mn, __shfl_xor_sync(0xffffffffu, mn, o));
        }
        if (lane == 0) {
            g_partials[blockIdx.x] = s;
            g_blockmin[blockIdx.x] = mn;
            __threadfence();
            unsigned int t = atomicAdd(&g_counter, 1u);
            sLast = ((t % gridDim.x) == gridDim.x - 1) ? 1 : 0;
        }
    }
    __syncthreads();
    if (!sLast) return;

    // ================= elected last block: final reduce =================
    float s  = 0.0f;
    int   mn = INT_MAX;
    for (int i = tid; i < (int)gridDim.x; i += THREADS) {
        s  += g_partials[i];
        mn  = min(mn, g_blockmin[i]);
    }
    #pragma unroll
    for (int o = 16; o > 0; o >>= 1) {
        s  += __shfl_xor_sync(0xffffffffu, s, o);
        mn  = min(mn, __shfl_xor_sync(0xffffffffu, mn, o));
    }
    __shared__ float fWs[WARPS];
    __shared__ int   fWm[WARPS];
    __shared__ int   sCut;
    if (lane == 0) { fWs[wid] = s; fWm[wid] = mn; }
    __syncthreads();
    if (tid < 32) {
        float s2  = (lane < WARPS) ? fWs[lane] : 0.0f;
        int   mn2 = (lane < WARPS) ? fWm[lane] : INT_MAX;
        #pragma unroll
        for (int o = 2; o > 0; o >>= 1) {
            s2  += __shfl_xor_sync(0xffffffffu, s2, o);
            mn2  = min(mn2, __shfl_xor_sync(0xffffffffu, mn2, o));
        }
        if (lane == 0) {
            int cutoff = min(mn2, K);
            sCut = cutoff;
            if (cutoff >= K) out[0] = s2;   // common path
        }
    }
    __syncthreads();

    // ---- rare fixup (P ~ 0.25^80): recompute prefix [0, cutoff) from gmem ----
    const int cutoff = sCut;
    if (cutoff < K) {
        float fs = 0.0f;
        for (int r = tid; r < cutoff; r += THREADS) {
            const float4* rr = reinterpret_cast<const float4*>(post + (size_t)r * 80);
            float mm = -FLT_MAX;
            #pragma unroll 5
            for (int i = 0; i < 20; i++) {
                float4 v = __ldg(rr + i);
                mm = fmaxf(mm, fmaxf(fmaxf(v.x, v.y), fmaxf(v.z, v.w)));
            }
            fs += mm;
        }
        #pragma unroll
        for (int o = 16; o > 0; o >>= 1)
            fs += __shfl_xor_sync(0xffffffffu, fs, o);
        if (lane == 0) fWs[wid] = fs;
        __syncthreads();
        if (tid < 32) {
            float f2 = (lane < WARPS) ? fWs[lane] : 0.0f;
            #pragma unroll
            for (int o = 2; o > 0; o >>= 1)
                f2 += __shfl_xor_sync(0xffffffffu, f2, o);
            if (lane == 0) out[0] = f2;
        }
    }
}

extern "C" void kernel_launch(void* const* d_in, const int* in_sizes, int n_in,
                              void* d_out, int out_size) {
    const float* post = (const float*)d_in[0];
    float* out = (float*)d_out;

    const int n_rows = in_sizes[0] / 80;   // 262144
    const int K      = n_rows / 2;         // ratio = 0.5 -> 131072

    const int blocks = (K + ROWS_PER_TILE - 1) / ROWS_PER_TILE;  // 2048
    fused_kernel<<<blocks, THREADS>>>(post, out, K);
}

// round 17
// speedup vs baseline: 1.0052x; 1.0052x over previous
#include <cuda_runtime.h>
#include <cstdint>
#include <float.h>
#include <limits.h>

#define CONF_THRESH   0.25f
#define ROWS_PER_TILE 64
#define ROWS_PER_WARP 16
#define TILE_FLOATS   (ROWS_PER_TILE * 80)      // 5120 floats = 20 KB
#define THREADS       128
#define WARPS         (THREADS / 32)            // 4

// Scratch (__device__ globals; no cudaMalloc allowed).
__device__ float        g_partials[4096];
__device__ int          g_blockmin[4096];
__device__ unsigned int g_counter = 0;          // modulo ticket: no reset needed

__device__ __forceinline__ uint32_t smem_u32(const void* p) {
    uint32_t a;
    asm("{ .reg .u64 t; cvta.to.shared.u64 t, %1; cvt.u32.u64 %0, t; }"
        : "=r"(a) : "l"(p));
    return a;
}

__global__ void __launch_bounds__(THREADS)
fused_kernel(const float* __restrict__ post, float* __restrict__ out, int K) {
    __shared__ alignas(16) float tile[TILE_FLOATS];
    __shared__ int   sLast;
    __shared__ float sWs[WARPS];
    __shared__ int   sWm[WARPS];

    const int tid  = threadIdx.x;
    const int lane = tid & 31;
    const int wid  = tid >> 5;

    // ================= warp-autonomous streaming: no __syncthreads =========
    // Warp w owns rows [w*16, (w+1)*16) of this block's 64-row tile.
    const int warp_rowbase = blockIdx.x * ROWS_PER_TILE + wid * ROWS_PER_WARP;

    // ---- stage own 16 rows (5120 B): 10 x 16B per lane, warp-private slice ----
    const float4* gsrc = reinterpret_cast<const float4*>(post) +
                         (size_t)warp_rowbase * 20;
    const uint32_t sslice = smem_u32(tile + wid * ROWS_PER_WARP * 80);
    #pragma unroll
    for (int k = 0; k < 10; k++) {
        const int idx = lane + k * 32;
        asm volatile("cp.async.cg.shared.global [%0], [%1], 16;"
                     :: "r"(sslice + idx * 16), "l"(gsrc + idx) : "memory");
    }
    asm volatile("cp.async.commit_group;" ::: "memory");
    asm volatile("cp.async.wait_group 0;" ::: "memory");
    __syncwarp();                     // intra-warp visibility of staged slice

    // ---- row maxes from own slice: 4 lanes per row, 5 LDS.128, 2 passes ----
    const int sub = lane & 3;         // quarter within a row
    const int r   = lane >> 2;        // 0..7
    float wsum = 0.0f;
    int   wmin = INT_MAX;

    #pragma unroll
    for (int j = 0; j < 2; j++) {
        const int lrow = j * 8 + r;                   // 0..15 within slice
        const int grow = warp_rowbase + lrow;
        const float4* rp = reinterpret_cast<const float4*>(
                               tile + (wid * ROWS_PER_WARP + lrow) * 80) + sub * 5;
        float m = -FLT_MAX;
        #pragma unroll
        for (int i = 0; i < 5; i++) {
            float4 v = rp[i];
            m = fmaxf(m, fmaxf(fmaxf(v.x, v.y), fmaxf(v.z, v.w)));
        }
        m = fmaxf(m, __shfl_xor_sync(0xffffffffu, m, 1));
        m = fmaxf(m, __shfl_xor_sync(0xffffffffu, m, 2));
        if (sub == 0 && grow < K) {
            wsum += m;
            if (m < CONF_THRESH) wmin = min(wmin, grow);
        }
    }

    // ---- warp reduce ----
    #pragma unroll
    for (int o = 16; o > 0; o >>= 1) {
        wsum += __shfl_xor_sync(0xffffffffu, wsum, o);
        wmin  = min(wmin, __shfl_xor_sync(0xffffffffu, wmin, o));
    }
    if (lane == 0) { sWs[wid] = wsum; sWm[wid] = wmin; }
    __syncthreads();                  // first block-wide barrier (post-stream)

    // ---- block reduce + ticket ----
    if (tid < 32) {
        float s  = (lane < WARPS) ? sWs[lane] : 0.0f;
        int   mn = (lane < WARPS) ? sWm[lane] : INT_MAX;
        #pragma unroll
        for (int o = 2; o > 0; o >>= 1) {
            s  += __shfl_xor_sync(0xffffffffu, s, o);
            mn  = min(mn, __shfl_xor_sync(0xffffffffu, mn, o));
        }
        if (lane == 0) {
            g_partials[blockIdx.x] = s;
            g_blockmin[blockIdx.x] = mn;
            __threadfence();
            unsigned int t = atomicAdd(&g_counter, 1u);
            sLast = ((t % gridDim.x) == gridDim.x - 1) ? 1 : 0;
        }
    }
    __syncthreads();
    if (!sLast) return;

    // ================= elected last block: final reduce =================
    float s  = 0.0f;
    int   mn = INT_MAX;
    for (int i = tid; i < (int)gridDim.x; i += THREADS) {
        s  += g_partials[i];
        mn  = min(mn, g_blockmin[i]);
    }
    #pragma unroll
    for (int o = 16; o > 0; o >>= 1) {
        s  += __shfl_xor_sync(0xffffffffu, s, o);
        mn  = min(mn, __shfl_xor_sync(0xffffffffu, mn, o));
    }
    __shared__ float fWs[WARPS];
    __shared__ int   fWm[WARPS];
    __shared__ int   sCut;
    if (lane == 0) { fWs[wid] = s; fWm[wid] = mn; }
    __syncthreads();
    if (tid < 32) {
        float s2  = (lane < WARPS) ? fWs[lane] : 0.0f;
        int   mn2 = (lane < WARPS) ? fWm[lane] : INT_MAX;
        #pragma unroll
        for (int o = 2; o > 0; o >>= 1) {
            s2  += __shfl_xor_sync(0xffffffffu, s2, o);
            mn2  = min(mn2, __shfl_xor_sync(0xffffffffu, mn2, o));
        }
        if (lane == 0) {
            int cutoff = min(mn2, K);
            sCut = cutoff;
            if (cutoff >= K) out[0] = s2;   // common path
        }
    }
    __syncthreads();

    // ---- rare fixup (P ~ 0.25^80): recompute prefix [0, cutoff) from gmem ----
    const int cutoff = sCut;
    if (cutoff < K) {
        float fs = 0.0f;
        for (int rr_ = tid; rr_ < cutoff; rr_ += THREADS) {
            const float4* rr = reinterpret_cast<const float4*>(post + (size_t)rr_ * 80);
            float mm = -FLT_MAX;
            #pragma unroll 5
            for (int i = 0; i < 20; i++) {
                float4 v = __ldg(rr + i);
                mm = fmaxf(mm, fmaxf(fmaxf(v.x, v.y), fmaxf(v.z, v.w)));
            }
            fs += mm;
        }
        #pragma unroll
        for (int o = 16; o > 0; o >>= 1)
            fs += __shfl_xor_sync(0xffffffffu, fs, o);
        if (lane == 0) fWs[wid] = fs;
        __syncthreads();
        if (tid < 32) {
            float f2 = (lane < WARPS) ? fWs[lane] : 0.0f;
            #pragma unroll
            for (int o = 2; o > 0; o >>= 1)
                f2 += __shfl_xor_sync(0xffffffffu, f2, o);
            if (lane == 0) out[0] = f2;
        }
    }
}

extern "C" void kernel_launch(void* const* d_in, const int* in_sizes, int n_in,
                              void* d_out, int out_size) {
    const float* post = (const float*)d_in[0];
    float* out = (float*)d_out;

    const int n_rows = in_sizes[0] / 80;   // 262144
    const int K      = n_rows / 2;         // ratio = 0.5 -> 131072

    const int blocks = (K + ROWS_PER_TILE - 1) / ROWS_PER_TILE;  // 2048
    fused_kernel<<<blocks, THREADS>>>(post, out, K);
}